// round 7
// baseline (speedup 1.0000x reference)
#include <cuda_runtime.h>
#include <cuda_bf16.h>

// Problem geometry (fixed by the dataset).
static constexpr int Dv = 160;
static constexpr int Hv = 192;
static constexpr int Wv = 160;
static constexpr int SH = Wv;           // stride of one h-row
static constexpr int SD = Hv * Wv;      // stride of one d-slice (30720)
static constexpr int V  = Dv * Hv * Wv; // 4,915,200 voxels
static constexpr int QV = V / 4;        // 1,228,800 = exactly 40 d-slices
static constexpr int DQ = Dv / 4;       // 40: d-stride between a thread's voxels

// Affine fold constants (double-evaluated, rounded to fp32).
// Stage B:  j = (coord + of*rf) * (S/(S-1)) - 0.5
static constexpr float CW = (float)(160.0 / 159.0);
static constexpr float CH = (float)(192.0 / 191.0);
static constexpr float CD = (float)(160.0 / 159.0);
// Stage A:  i = ((g+1)*S - 1) * 0.5 = g*(S/2) + (S-1)/2
static constexpr float AW = 80.0f,  BW = 79.5f;
static constexpr float AH = 96.0f,  BH = 95.5f;
static constexpr float AD = 80.0f,  BD = 79.5f;

// ---------------------------------------------------------------------------
// Trilinear sample of the single-channel src volume, zeros padding.
// Interior fast path: one base pointer + 8 constant-offset loads.
// ---------------------------------------------------------------------------
__device__ __forceinline__ float samp_src(const float* __restrict__ v,
                                          float ix, float iy, float iz) {
    float xf = floorf(ix), yf = floorf(iy), zf = floorf(iz);
    float tx = ix - xf,    ty = iy - yf,    tz = iz - zf;
    int   x0 = (int)xf,    y0 = (int)yf,    z0 = (int)zf;

    float wx0 = 1.0f - tx, wy0 = 1.0f - ty, wz0 = 1.0f - tz;
    float a = wz0 * wy0;   // z0,y0
    float b = wz0 * ty;    // z0,y1
    float c = tz  * wy0;   // z1,y0
    float e = tz  * ty;    // z1,y1

    bool bx0 = (unsigned)x0       < (unsigned)Wv;
    bool bx1 = (unsigned)(x0 + 1) < (unsigned)Wv;
    bool by0 = (unsigned)y0       < (unsigned)Hv;
    bool by1 = (unsigned)(y0 + 1) < (unsigned)Hv;
    bool bz0 = (unsigned)z0       < (unsigned)Dv;
    bool bz1 = (unsigned)(z0 + 1) < (unsigned)Dv;

    if (bx0 & bx1 & by0 & by1 & bz0 & bz1) {
        const float* p = v + ((z0 * Hv + y0) * Wv + x0);
        float acc;
        acc  = p[0]           * (a * wx0);
        acc += p[1]           * (a * tx );
        acc += p[SH]          * (b * wx0);
        acc += p[SH + 1]      * (b * tx );
        acc += p[SD]          * (c * wx0);
        acc += p[SD + 1]      * (c * tx );
        acc += p[SD + SH]     * (e * wx0);
        acc += p[SD + SH + 1] * (e * tx );
        return acc;
    }

    // Boundary path: clamp indices + zero-mask weights (reference-equivalent).
    int cx0 = min(max(x0,     0), Wv - 1), cx1 = min(max(x0 + 1, 0), Wv - 1);
    int cy0 = min(max(y0,     0), Hv - 1), cy1 = min(max(y0 + 1, 0), Hv - 1);
    int cz0 = min(max(z0,     0), Dv - 1), cz1 = min(max(z0 + 1, 0), Dv - 1);

    float acc = 0.0f;
    acc += v[(cz0 * Hv + cy0) * Wv + cx0] * ((a * wx0) * ((bz0 & by0 & bx0) ? 1.0f : 0.0f));
    acc += v[(cz0 * Hv + cy0) * Wv + cx1] * ((a * tx ) * ((bz0 & by0 & bx1) ? 1.0f : 0.0f));
    acc += v[(cz0 * Hv + cy1) * Wv + cx0] * ((b * wx0) * ((bz0 & by1 & bx0) ? 1.0f : 0.0f));
    acc += v[(cz0 * Hv + cy1) * Wv + cx1] * ((b * tx ) * ((bz0 & by1 & bx1) ? 1.0f : 0.0f));
    acc += v[(cz1 * Hv + cy0) * Wv + cx0] * ((c * wx0) * ((bz1 & by0 & bx0) ? 1.0f : 0.0f));
    acc += v[(cz1 * Hv + cy0) * Wv + cx1] * ((c * tx ) * ((bz1 & by0 & bx1) ? 1.0f : 0.0f));
    acc += v[(cz1 * Hv + cy1) * Wv + cx0] * ((e * wx0) * ((bz1 & by1 & bx0) ? 1.0f : 0.0f));
    acc += v[(cz1 * Hv + cy1) * Wv + cx1] * ((e * tx ) * ((bz1 & by1 & bx1) ? 1.0f : 0.0f));
    return acc;
}

// ---------------------------------------------------------------------------
// Trilinear sample of the 3-channel flow1 volume, zeros padding.
// The reference feeds RAW voxel coordinates through the [-1,1] unnormalizer,
// so this is fully out of bounds for essentially every voxel. Caller performs
// the cheap fully-out test; this is the rare slow path.
// ---------------------------------------------------------------------------
__device__ __noinline__ void samp_flow(const float* __restrict__ f,
                                       float ix, float iy, float iz,
                                       float& o0, float& o1, float& o2) {
    float xf = floorf(ix), yf = floorf(iy), zf = floorf(iz);
    int   x0 = (int)xf,    y0 = (int)yf,    z0 = (int)zf;

    float tx = ix - xf, ty = iy - yf, tz = iz - zf;
    float wx0 = 1.0f - tx, wy0 = 1.0f - ty, wz0 = 1.0f - tz;
    float a = wz0 * wy0, b = wz0 * ty, c = tz * wy0, e = tz * ty;

    bool bx0 = (unsigned)x0       < (unsigned)Wv;
    bool bx1 = (unsigned)(x0 + 1) < (unsigned)Wv;
    bool by0 = (unsigned)y0       < (unsigned)Hv;
    bool by1 = (unsigned)(y0 + 1) < (unsigned)Hv;
    bool bz0 = (unsigned)z0       < (unsigned)Dv;
    bool bz1 = (unsigned)(z0 + 1) < (unsigned)Dv;

    int cx0 = min(max(x0,     0), Wv - 1), cx1 = min(max(x0 + 1, 0), Wv - 1);
    int cy0 = min(max(y0,     0), Hv - 1), cy1 = min(max(y0 + 1, 0), Hv - 1);
    int cz0 = min(max(z0,     0), Dv - 1), cz1 = min(max(z0 + 1, 0), Dv - 1);

    int   idx[8];
    float wgt[8];
    idx[0] = (cz0 * Hv + cy0) * Wv + cx0; wgt[0] = (a * wx0) * ((bz0 & by0 & bx0) ? 1.0f : 0.0f);
    idx[1] = (cz0 * Hv + cy0) * Wv + cx1; wgt[1] = (a * tx ) * ((bz0 & by0 & bx1) ? 1.0f : 0.0f);
    idx[2] = (cz0 * Hv + cy1) * Wv + cx0; wgt[2] = (b * wx0) * ((bz0 & by1 & bx0) ? 1.0f : 0.0f);
    idx[3] = (cz0 * Hv + cy1) * Wv + cx1; wgt[3] = (b * tx ) * ((bz0 & by1 & bx1) ? 1.0f : 0.0f);
    idx[4] = (cz1 * Hv + cy0) * Wv + cx0; wgt[4] = (c * wx0) * ((bz1 & by0 & bx0) ? 1.0f : 0.0f);
    idx[5] = (cz1 * Hv + cy0) * Wv + cx1; wgt[5] = (c * tx ) * ((bz1 & by0 & bx1) ? 1.0f : 0.0f);
    idx[6] = (cz1 * Hv + cy1) * Wv + cx0; wgt[6] = (e * wx0) * ((bz1 & by1 & bx0) ? 1.0f : 0.0f);
    idx[7] = (cz1 * Hv + cy1) * Wv + cx1; wgt[7] = (e * tx ) * ((bz1 & by1 & bx1) ? 1.0f : 0.0f);

    float s0 = 0.f, s1 = 0.f, s2 = 0.f;
#pragma unroll
    for (int k = 0; k < 8; k++) {
        float wk = wgt[k];
        int   ik = idx[k];
        s0 += f[ik]         * wk;
        s1 += f[V + ik]     * wk;
        s2 += f[2 * V + ik] * wk;
    }
    o0 = s0; o1 = s1; o2 = s2;
}

// ---------------------------------------------------------------------------
// Fused kernel: 4 voxels per thread, strided by QV = V/4 (= exactly 40
// d-slices). Thread t handles voxels (d0+40k, h, w), k=0..3: same (h,w),
// warp lanes stay x-consecutive -> gather coalescing unchanged, 4x MLP.
//   out[0 : V ) = deform_2_img
//   out[V : 2V) = out_flow ch0 (d)
//   out[2V: 3V) = out_flow ch1 (h)
//   out[3V: 4V) = out_flow ch2 (w)
// ---------------------------------------------------------------------------
__global__ void __launch_bounds__(256)
spatial_transformer_fused4(const float* __restrict__ src,
                           const float* __restrict__ flow1,
                           const float* __restrict__ flow2,
                           const float* __restrict__ rf_ptr,
                           float* __restrict__ out) {
    int t = blockIdx.x * blockDim.x + threadIdx.x;   // 0 .. QV-1
    const float rf = __ldg(rf_ptr);

    int w  = t % Wv;
    int r  = t / Wv;
    int h  = r % Hv;
    int d0 = r / Hv;                                  // 0 .. 39

    const float fw = (float)w;
    const float fh = (float)h;

    // Batch all flow2 loads up front for maximal MLP.
    float f2d[4], f2h[4], f2w[4];
#pragma unroll
    for (int k = 0; k < 4; k++) {
        int p = t + k * QV;
        f2d[k] = flow2[p];
        f2h[k] = flow2[V + p];
        f2w[k] = flow2[2 * V + p];
    }

#pragma unroll
    for (int k = 0; k < 4; k++) {
        const int   p  = t + k * QV;
        const float fd = (float)(d0 + k * DQ);

        // Stage A: grid2 = grid + flow2*rf (raw voxel coords) pushed through
        // the align_corners=False unnormalizer (bug-compatible): i = g*S/2 + (S-1)/2.
        float gz = fmaf(f2d[k], rf, fd);
        float gy = fmaf(f2h[k], rf, fh);
        float gx = fmaf(f2w[k], rf, fw);

        float ix = fmaf(gx, AW, BW);
        float iy = fmaf(gy, AH, BH);
        float iz = fmaf(gz, AD, BD);

        // Fully-out test without floor: floor(i) < -1  <=>  i < -1 ;
        // floor(i) >= S  <=>  i >= S. Zero padding kills all 8 corners.
        float fw0 = 0.f, fw1 = 0.f, fw2 = 0.f;
        if (!(ix < -1.0f || ix >= (float)Wv ||
              iy < -1.0f || iy >= (float)Hv ||
              iz < -1.0f || iz >= (float)Dv)) {
            samp_flow(flow1, ix, iy, iz, fw0, fw1, fw2);
        }

        float ofd = fw0 + f2d[k];
        float ofh = fw1 + f2h[k];
        float ofw = fw2 + f2w[k];

        // Stage B folded affine: j = (coord + of*rf) * S/(S-1) - 0.5
        float jz = fmaf(fmaf(ofd, rf, fd), CD, -0.5f);
        float jy = fmaf(fmaf(ofh, rf, fh), CH, -0.5f);
        float jx = fmaf(fmaf(ofw, rf, fw), CW, -0.5f);

        float img = samp_src(src, jx, jy, jz);

        out[p]         = img;
        out[V + p]     = ofd;
        out[2 * V + p] = ofh;
        out[3 * V + p] = ofw;
    }
}

extern "C" void kernel_launch(void* const* d_in, const int* in_sizes, int n_in,
                              void* d_out, int out_size) {
    // metadata order: src, flow1, flow2, grid (unused: analytic meshgrid),
    // range_flow (device scalar).
    const float* src   = (const float*)d_in[0];
    const float* flow1 = (const float*)d_in[1];
    const float* flow2 = (const float*)d_in[2];
    const float* rf    = (const float*)d_in[4];
    float* out = (float*)d_out;

    const int threads = 256;
    const int blocks  = QV / threads; // 4800
    spatial_transformer_fused4<<<blocks, threads>>>(src, flow1, flow2, rf, out);
}

// round 8
// speedup vs baseline: 1.0876x; 1.0876x over previous
#include <cuda_runtime.h>
#include <cuda_bf16.h>

// Problem geometry (fixed by the dataset).
static constexpr int Dv = 160;
static constexpr int Hv = 192;
static constexpr int Wv = 160;
static constexpr int SH = Wv;           // stride of one h-row
static constexpr int SD = Hv * Wv;      // stride of one d-slice (30720)
static constexpr int V  = Dv * Hv * Wv; // 4,915,200 voxels
static constexpr int HALF = V / 2;      // threads (2 consecutive-x voxels each)

// Affine fold constants (double-evaluated, rounded to fp32).
// Stage B:  j = (coord + of*rf) * (S/(S-1)) - 0.5
static constexpr float CW = (float)(160.0 / 159.0);
static constexpr float CH = (float)(192.0 / 191.0);
static constexpr float CD = (float)(160.0 / 159.0);
// Stage A:  i = ((g+1)*S - 1) * 0.5 = g*(S/2) + (S-1)/2
static constexpr float AW = 80.0f,  BW = 79.5f;
static constexpr float AH = 96.0f,  BH = 95.5f;
static constexpr float AD = 80.0f,  BD = 79.5f;

// ---------------------------------------------------------------------------
// Trilinear sample of the single-channel src volume, zeros padding.
// Interior fast path: one base pointer + 8 constant-offset loads.
// ---------------------------------------------------------------------------
__device__ __forceinline__ float samp_src(const float* __restrict__ v,
                                          float ix, float iy, float iz) {
    float xf = floorf(ix), yf = floorf(iy), zf = floorf(iz);
    float tx = ix - xf,    ty = iy - yf,    tz = iz - zf;
    int   x0 = (int)xf,    y0 = (int)yf,    z0 = (int)zf;

    float wx0 = 1.0f - tx, wy0 = 1.0f - ty, wz0 = 1.0f - tz;
    float a = wz0 * wy0;   // z0,y0
    float b = wz0 * ty;    // z0,y1
    float c = tz  * wy0;   // z1,y0
    float e = tz  * ty;    // z1,y1

    bool bx0 = (unsigned)x0       < (unsigned)Wv;
    bool bx1 = (unsigned)(x0 + 1) < (unsigned)Wv;
    bool by0 = (unsigned)y0       < (unsigned)Hv;
    bool by1 = (unsigned)(y0 + 1) < (unsigned)Hv;
    bool bz0 = (unsigned)z0       < (unsigned)Dv;
    bool bz1 = (unsigned)(z0 + 1) < (unsigned)Dv;

    if (bx0 & bx1 & by0 & by1 & bz0 & bz1) {
        const float* p = v + ((z0 * Hv + y0) * Wv + x0);
        float acc;
        acc  = p[0]           * (a * wx0);
        acc += p[1]           * (a * tx );
        acc += p[SH]          * (b * wx0);
        acc += p[SH + 1]      * (b * tx );
        acc += p[SD]          * (c * wx0);
        acc += p[SD + 1]      * (c * tx );
        acc += p[SD + SH]     * (e * wx0);
        acc += p[SD + SH + 1] * (e * tx );
        return acc;
    }

    // Boundary path: clamp indices + zero-mask weights (reference-equivalent).
    int cx0 = min(max(x0,     0), Wv - 1), cx1 = min(max(x0 + 1, 0), Wv - 1);
    int cy0 = min(max(y0,     0), Hv - 1), cy1 = min(max(y0 + 1, 0), Hv - 1);
    int cz0 = min(max(z0,     0), Dv - 1), cz1 = min(max(z0 + 1, 0), Dv - 1);

    float acc = 0.0f;
    acc += v[(cz0 * Hv + cy0) * Wv + cx0] * ((a * wx0) * ((bz0 & by0 & bx0) ? 1.0f : 0.0f));
    acc += v[(cz0 * Hv + cy0) * Wv + cx1] * ((a * tx ) * ((bz0 & by0 & bx1) ? 1.0f : 0.0f));
    acc += v[(cz0 * Hv + cy1) * Wv + cx0] * ((b * wx0) * ((bz0 & by1 & bx0) ? 1.0f : 0.0f));
    acc += v[(cz0 * Hv + cy1) * Wv + cx1] * ((b * tx ) * ((bz0 & by1 & bx1) ? 1.0f : 0.0f));
    acc += v[(cz1 * Hv + cy0) * Wv + cx0] * ((c * wx0) * ((bz1 & by0 & bx0) ? 1.0f : 0.0f));
    acc += v[(cz1 * Hv + cy0) * Wv + cx1] * ((c * tx ) * ((bz1 & by0 & bx1) ? 1.0f : 0.0f));
    acc += v[(cz1 * Hv + cy1) * Wv + cx0] * ((e * wx0) * ((bz1 & by1 & bx0) ? 1.0f : 0.0f));
    acc += v[(cz1 * Hv + cy1) * Wv + cx1] * ((e * tx ) * ((bz1 & by1 & bx1) ? 1.0f : 0.0f));
    return acc;
}

// ---------------------------------------------------------------------------
// Trilinear sample of the 3-channel flow1 volume, zeros padding. The
// reference feeds RAW voxel coordinates through the [-1,1] unnormalizer, so
// this is fully out of bounds for essentially every voxel. Caller performs
// the cheap fully-out test; this is the rare slow path (kept out of line so
// its registers don't bloat the hot path).
// ---------------------------------------------------------------------------
__device__ __noinline__ void samp_flow(const float* __restrict__ f,
                                       float ix, float iy, float iz,
                                       float& o0, float& o1, float& o2) {
    float xf = floorf(ix), yf = floorf(iy), zf = floorf(iz);
    int   x0 = (int)xf,    y0 = (int)yf,    z0 = (int)zf;

    float tx = ix - xf, ty = iy - yf, tz = iz - zf;
    float wx0 = 1.0f - tx, wy0 = 1.0f - ty, wz0 = 1.0f - tz;
    float a = wz0 * wy0, b = wz0 * ty, c = tz * wy0, e = tz * ty;

    bool bx0 = (unsigned)x0       < (unsigned)Wv;
    bool bx1 = (unsigned)(x0 + 1) < (unsigned)Wv;
    bool by0 = (unsigned)y0       < (unsigned)Hv;
    bool by1 = (unsigned)(y0 + 1) < (unsigned)Hv;
    bool bz0 = (unsigned)z0       < (unsigned)Dv;
    bool bz1 = (unsigned)(z0 + 1) < (unsigned)Dv;

    int cx0 = min(max(x0,     0), Wv - 1), cx1 = min(max(x0 + 1, 0), Wv - 1);
    int cy0 = min(max(y0,     0), Hv - 1), cy1 = min(max(y0 + 1, 0), Hv - 1);
    int cz0 = min(max(z0,     0), Dv - 1), cz1 = min(max(z0 + 1, 0), Dv - 1);

    int   idx[8];
    float wgt[8];
    idx[0] = (cz0 * Hv + cy0) * Wv + cx0; wgt[0] = (a * wx0) * ((bz0 & by0 & bx0) ? 1.0f : 0.0f);
    idx[1] = (cz0 * Hv + cy0) * Wv + cx1; wgt[1] = (a * tx ) * ((bz0 & by0 & bx1) ? 1.0f : 0.0f);
    idx[2] = (cz0 * Hv + cy1) * Wv + cx0; wgt[2] = (b * wx0) * ((bz0 & by1 & bx0) ? 1.0f : 0.0f);
    idx[3] = (cz0 * Hv + cy1) * Wv + cx1; wgt[3] = (b * tx ) * ((bz0 & by1 & bx1) ? 1.0f : 0.0f);
    idx[4] = (cz1 * Hv + cy0) * Wv + cx0; wgt[4] = (c * wx0) * ((bz1 & by0 & bx0) ? 1.0f : 0.0f);
    idx[5] = (cz1 * Hv + cy0) * Wv + cx1; wgt[5] = (c * tx ) * ((bz1 & by0 & bx1) ? 1.0f : 0.0f);
    idx[6] = (cz1 * Hv + cy1) * Wv + cx0; wgt[6] = (e * wx0) * ((bz1 & by1 & bx0) ? 1.0f : 0.0f);
    idx[7] = (cz1 * Hv + cy1) * Wv + cx1; wgt[7] = (e * tx ) * ((bz1 & by1 & bx1) ? 1.0f : 0.0f);

    float s0 = 0.f, s1 = 0.f, s2 = 0.f;
#pragma unroll
    for (int k = 0; k < 8; k++) {
        float wk = wgt[k];
        int   ik = idx[k];
        s0 += f[ik]         * wk;
        s1 += f[V + ik]     * wk;
        s2 += f[2 * V + ik] * wk;
    }
    o0 = s0; o1 = s1; o2 = s2;
}

// ---------------------------------------------------------------------------
// One voxel of the fused pipeline (coordinates -> out_flow + sampled image).
// ---------------------------------------------------------------------------
__device__ __forceinline__ void do_voxel(const float* __restrict__ src,
                                         const float* __restrict__ flow1,
                                         float fw_, float fh_, float fd_,
                                         float f2d, float f2h, float f2w,
                                         float rf,
                                         float& img, float& ofd, float& ofh, float& ofw) {
    // Stage A: grid2 = grid + flow2*rf (raw voxel coords) pushed through the
    // align_corners=False unnormalizer (bug-compatible): i = g*S/2 + (S-1)/2.
    float gz = fmaf(f2d, rf, fd_);
    float gy = fmaf(f2h, rf, fh_);
    float gx = fmaf(f2w, rf, fw_);

    float ix = fmaf(gx, AW, BW);
    float iy = fmaf(gy, AH, BH);
    float iz = fmaf(gz, AD, BD);

    // Fully-out test without floor: floor(i) < -1 <=> i < -1 ; floor(i) >= S
    // <=> i >= S. Zero padding kills all 8 corners.
    float fw0 = 0.f, fw1 = 0.f, fw2 = 0.f;
    if (!(ix < -1.0f || ix >= (float)Wv ||
          iy < -1.0f || iy >= (float)Hv ||
          iz < -1.0f || iz >= (float)Dv)) {
        samp_flow(flow1, ix, iy, iz, fw0, fw1, fw2);
    }

    ofd = fw0 + f2d;
    ofh = fw1 + f2h;
    ofw = fw2 + f2w;

    // Stage B folded affine: j = (coord + of*rf) * S/(S-1) - 0.5
    float jz = fmaf(fmaf(ofd, rf, fd_), CD, -0.5f);
    float jy = fmaf(fmaf(ofh, rf, fh_), CH, -0.5f);
    float jx = fmaf(fmaf(ofw, rf, fw_), CW, -0.5f);

    img = samp_src(src, jx, jy, jz);
}

// ---------------------------------------------------------------------------
// Fused kernel: 2 consecutive-x voxels per thread (p = 2t, 2t+1). W = 160 is
// even, so a pair never crosses a row; V is even, so every channel plane and
// output plane stays 8-byte aligned for float2 loads/stores.
// Mem instrs/voxel: 8 gathers + 1.5 LDG.64 + 2 STG.64 = 11.5 (was 15).
//   out[0 : V ) = deform_2_img
//   out[V : 2V) = out_flow ch0 (d)
//   out[2V: 3V) = out_flow ch1 (h)
//   out[3V: 4V) = out_flow ch2 (w)
// ---------------------------------------------------------------------------
__global__ void __launch_bounds__(256)
spatial_transformer_pair(const float* __restrict__ src,
                         const float* __restrict__ flow1,
                         const float* __restrict__ flow2,
                         const float* __restrict__ rf_ptr,
                         float* __restrict__ out) {
    int t = blockIdx.x * blockDim.x + threadIdx.x;   // 0 .. HALF-1
    const float rf = __ldg(rf_ptr);

    const int p = 2 * t;              // even voxel index
    int w = p % Wv;                   // even, pair stays in-row
    int r = p / Wv;
    int h = r % Hv;
    int d = r / Hv;

    const float fw_ = (float)w;
    const float fh_ = (float)h;
    const float fd_ = (float)d;

    // Vectorized flow2 loads (8B-aligned: p even, V even).
    float2 F2d = *reinterpret_cast<const float2*>(flow2 + p);
    float2 F2h = *reinterpret_cast<const float2*>(flow2 + V + p);
    float2 F2w = *reinterpret_cast<const float2*>(flow2 + 2 * V + p);

    float img0, ofd0, ofh0, ofw0;
    float img1, ofd1, ofh1, ofw1;

    do_voxel(src, flow1, fw_,        fh_, fd_, F2d.x, F2h.x, F2w.x, rf,
             img0, ofd0, ofh0, ofw0);
    do_voxel(src, flow1, fw_ + 1.0f, fh_, fd_, F2d.y, F2h.y, F2w.y, rf,
             img1, ofd1, ofh1, ofw1);

    // Vectorized stores.
    *reinterpret_cast<float2*>(out + p)         = make_float2(img0, img1);
    *reinterpret_cast<float2*>(out + V + p)     = make_float2(ofd0, ofd1);
    *reinterpret_cast<float2*>(out + 2 * V + p) = make_float2(ofh0, ofh1);
    *reinterpret_cast<float2*>(out + 3 * V + p) = make_float2(ofw0, ofw1);
}

extern "C" void kernel_launch(void* const* d_in, const int* in_sizes, int n_in,
                              void* d_out, int out_size) {
    // metadata order: src, flow1, flow2, grid (unused: analytic meshgrid),
    // range_flow (device scalar).
    const float* src   = (const float*)d_in[0];
    const float* flow1 = (const float*)d_in[1];
    const float* flow2 = (const float*)d_in[2];
    const float* rf    = (const float*)d_in[4];
    float* out = (float*)d_out;

    const int threads = 256;
    const int blocks  = HALF / threads; // 9600
    spatial_transformer_pair<<<blocks, threads>>>(src, flow1, flow2, rf, out);
}